// round 13
// baseline (speedup 1.0000x reference)
#include <cuda_runtime.h>
#include <cuda_bf16.h>
#include <cstdint>
#include <math.h>

#define HEADS 16
#define DH    64
#define SEQ   2048
#define BATCH 2
#define DIM   1024
#define BH    (BATCH*HEADS)
#define NOUT  3072   // 3*HEADS*DH
#define MTOT  (BATCH*SEQ)   // 4096

// bf16 copies of the inputs (written by cvt_kernel each call)
__device__ __nv_bfloat16 g_xb[MTOT * DIM];
__device__ __nv_bfloat16 g_wb[DIM * NOUT];
// bf16 q/k/v from QKV GEMM epilogue: q pre-scaled by 1/8; all [bh][n][64].
__device__ __nv_bfloat16 g_qb[BH * SEQ * DH];
__device__ __nv_bfloat16 g_kb[BH * SEQ * DH];
__device__ __nv_bfloat16 g_vb[BH * SEQ * DH];

__device__ __forceinline__ uint32_t smem_u32(const void* p) {
    uint32_t a;
    asm("{ .reg .u64 t; cvta.to.shared.u64 t, %1; cvt.u32.u64 %0, t; }"
        : "=r"(a) : "l"(p));
    return a;
}
#define SW128(b) ((b) ^ (((b) >> 3) & 0x70))

#define LDSM_X4(r0, r1, r2, r3, a)                                         \
    asm volatile("ldmatrix.sync.aligned.m8n8.x4.shared.b16 {%0,%1,%2,%3}, [%4];" \
        : "=r"(r0), "=r"(r1), "=r"(r2), "=r"(r3) : "r"(a))
#define LDSM_X4T(r0, r1, r2, r3, a)                                        \
    asm volatile("ldmatrix.sync.aligned.m8n8.x4.trans.shared.b16 {%0,%1,%2,%3}, [%4];" \
        : "=r"(r0), "=r"(r1), "=r"(r2), "=r"(r3) : "r"(a))

#define MMA_BF16(c, a, b0, b1)                                             \
    asm volatile("mma.sync.aligned.m16n8k16.row.col.f32.bf16.bf16.f32 "    \
        "{%0,%1,%2,%3}, {%4,%5,%6,%7}, {%8,%9}, {%0,%1,%2,%3};"            \
        : "+f"((c)[0]), "+f"((c)[1]), "+f"((c)[2]), "+f"((c)[3])           \
        : "r"((a)[0]), "r"((a)[1]), "r"((a)[2]), "r"((a)[3]),              \
          "r"(b0), "r"(b1))

#define CVT_BF2(res, lo, hi) \
    asm("cvt.rn.bf16x2.f32 %0, %1, %2;" : "=r"(res) : "f"(hi), "f"(lo))

#define CP16(dst, src) \
    asm volatile("cp.async.cg.shared.global [%0], [%1], 16;" :: "r"(dst), "l"(src) : "memory")
#define CP_COMMIT() asm volatile("cp.async.commit_group;" ::: "memory")
#define CP_WAIT1()  asm volatile("cp.async.wait_group 1;" ::: "memory")
#define CP_WAIT0()  asm volatile("cp.async.wait_group 0;" ::: "memory")

// ---------------------------------------------------------------------------
// Kernel 0: fp32 -> bf16 conversion of x and W (8 elems / thread).
// ---------------------------------------------------------------------------
#define NX8 (MTOT * DIM / 8)     // 524288
#define NW8 (DIM * NOUT / 8)     // 393216
__global__ __launch_bounds__(256)
void cvt_kernel(const float* __restrict__ x, const float* __restrict__ W) {
    int i = blockIdx.x * blockDim.x + threadIdx.x;
    const float4* s4;
    uint4* d4;
    int j;
    if (i < NX8) {
        s4 = (const float4*)x; d4 = (uint4*)g_xb; j = i;
    } else if (i < NX8 + NW8) {
        s4 = (const float4*)W; d4 = (uint4*)g_wb; j = i - NX8;
    } else return;
    float4 a = s4[2 * j], b = s4[2 * j + 1];
    uint4 o;
    CVT_BF2(o.x, a.x, a.y);
    CVT_BF2(o.y, a.z, a.w);
    CVT_BF2(o.z, b.x, b.y);
    CVT_BF2(o.w, b.z, b.w);
    d4[j] = o;
}

// ---------------------------------------------------------------------------
// Kernel 1: QKV GEMM, bf16 HMMA, 3-stage cp.async pipeline (unchanged).
// CTA tile 128x256, k-step 64, 512 threads = 16 warps (4m x 4n), warp 32x64.
// ---------------------------------------------------------------------------
#define GSTG 49152
#define NKB  (DIM / 64)   // 16

__global__ __launch_bounds__(512, 1)
void qkv_gemm(int dummy) {
    extern __shared__ __align__(1024) char smem[];
    const uint32_t sbase = smem_u32(smem);

    const int tid  = threadIdx.x;
    const int lane = tid & 31;
    const int warp = tid >> 5;
    const int wm = warp >> 2;
    const int wn = warp & 3;
    const int g  = lane >> 3;
    const int rl = lane & 7;
    const int gid = lane >> 2;
    const int tid4 = lane & 3;

    const int n0 = blockIdx.x * 256;
    const int m0 = blockIdx.y * 128;

    const int arow = tid >> 2;
    const int ac2  = (tid & 3) * 2;
    const int brow = tid >> 3;
    const int bseg = tid & 7;

    const char* Ag = (const char*)(g_xb + (size_t)(m0 + arow) * DIM);
    const char* Bg = (const char*)(g_wb + (size_t)brow * NOUT + n0 + bseg * 32);

    uint32_t sa_off[2], sb_off[4];
    #pragma unroll
    for (int j = 0; j < 2; ++j)
        sa_off[j] = SW128(arow * 128 + (ac2 + j) * 16);
    #pragma unroll
    for (int j = 0; j < 4; ++j)
        sb_off[j] = 16384 + (bseg >> 1) * 8192 +
                    SW128(brow * 128 + (bseg & 1) * 64 + j * 16);

    float c[2][8][4];
    #pragma unroll
    for (int mi = 0; mi < 2; ++mi)
        #pragma unroll
        for (int nj = 0; nj < 8; ++nj)
            #pragma unroll
            for (int i = 0; i < 4; ++i) c[mi][nj][i] = 0.f;

    uint32_t a_off[2], b_off[4];
    #pragma unroll
    for (int mi = 0; mi < 2; ++mi) {
        int row = wm * 32 + mi * 16 + (g & 1) * 8 + rl;
        a_off[mi] = SW128(row * 128 + (g >> 1) * 16);
    }
    #pragma unroll
    for (int nj = 0; nj < 4; ++nj) {
        int row = (g & 1) * 8 + rl;
        b_off[nj] = 16384 + wn * 8192 + SW128(row * 128 + nj * 32 + (g >> 1) * 16);
    }

    #pragma unroll
    for (int p = 0; p < 2; ++p) {
        uint32_t sb = sbase + p * GSTG;
        const char* As = Ag + p * 128;
        const char* Bs = Bg + (size_t)p * 64 * NOUT * 2;
        #pragma unroll
        for (int j = 0; j < 2; ++j) CP16(sb + sa_off[j], As + (ac2 + j) * 16);
        #pragma unroll
        for (int j = 0; j < 4; ++j) CP16(sb + sb_off[j], Bs + j * 16);
        CP_COMMIT();
    }

    for (int kb = 0; kb < NKB; ++kb) {
        if (kb == NKB - 1) { CP_WAIT0(); } else { CP_WAIT1(); }
        __syncthreads();

        if (kb + 2 < NKB) {
            int t = kb + 2;
            uint32_t sb = sbase + (t % 3) * GSTG;
            const char* As = Ag + t * 128;
            const char* Bs = Bg + (size_t)t * 64 * NOUT * 2;
            #pragma unroll
            for (int j = 0; j < 2; ++j) CP16(sb + sa_off[j], As + (ac2 + j) * 16);
            #pragma unroll
            for (int j = 0; j < 4; ++j) CP16(sb + sb_off[j], Bs + j * 16);
            CP_COMMIT();
        }

        const uint32_t stg = sbase + (kb % 3) * GSTG;
        #pragma unroll
        for (int kk = 0; kk < 4; ++kk) {
            uint32_t a[2][4];
            uint32_t kadd = (uint32_t)((kk * 32) ^ (((kk * 32) >> 3) & 0x70));
            #pragma unroll
            for (int mi = 0; mi < 2; ++mi) {
                LDSM_X4(a[mi][0], a[mi][1], a[mi][2], a[mi][3],
                        stg + (a_off[mi] ^ kadd));
            }
            #pragma unroll
            for (int nj = 0; nj < 4; ++nj) {
                uint32_t addr = stg + b_off[nj] + kk * 16 * 128;
                uint32_t b0, b1, b2, b3;
                LDSM_X4T(b0, b1, b2, b3, addr);
                MMA_BF16(c[0][2 * nj],     a[0], b0, b1);
                MMA_BF16(c[0][2 * nj + 1], a[0], b2, b3);
                MMA_BF16(c[1][2 * nj],     a[1], b0, b1);
                MMA_BF16(c[1][2 * nj + 1], a[1], b2, b3);
            }
        }
    }

    const int sec = n0 >> 10;
    const float s = (sec == 0) ? 0.125f : 1.0f;
    __nv_bfloat16* gout = (sec == 0) ? g_qb : (sec == 1) ? g_kb : g_vb;
    const int hh = ((n0 & 1023) >> 6) + wn;

    #pragma unroll
    for (int mi = 0; mi < 2; ++mi) {
        #pragma unroll
        for (int r8 = 0; r8 < 2; ++r8) {
            int m = m0 + wm * 32 + mi * 16 + r8 * 8 + gid;
            int bb = m >> 11;
            int n  = m & (SEQ - 1);
            __nv_bfloat16* dst =
                gout + ((size_t)(bb * HEADS + hh) * SEQ + n) * DH + tid4 * 2;
            #pragma unroll
            for (int nj = 0; nj < 8; ++nj) {
                uint32_t p;
                CVT_BF2(p, c[mi][nj][r8 * 2] * s, c[mi][nj][r8 * 2 + 1] * s);
                *(uint32_t*)(dst + nj * 8) = p;
            }
        }
    }
}

// ---------------------------------------------------------------------------
// Kernel 2: HMMA flash attention. CTA = (bh, 128-q tile), 128 threads =
// 4 warps x 32 q-rows (B-fragments amortized over 2x rows -> half the LDSM
// traffic). 128-key tiles as two 64-key halves with PV0||S1 interleave.
// 3-stage cp.async; smem = Q 16KB + 3 x 32KB = 112KB; 2 CTAs/SM.
// ---------------------------------------------------------------------------
#define ASTG2 32768
#define NT2   (SEQ / 128)   // 16

__global__ __launch_bounds__(128, 2)
void attn_mma(const float* __restrict__ x, float* __restrict__ out) {
    extern __shared__ __align__(1024) char smem[];
    const uint32_t sbase = smem_u32(smem);

    const int tid  = threadIdx.x;
    const int lane = tid & 31;
    const int warp = tid >> 5;        // 0..3, owns q-rows warp*32..warp*32+31
    const int g    = lane >> 3;
    const int rl   = lane & 7;
    const int gid  = lane >> 2;
    const int tid4 = lane & 3;

    const int bh = blockIdx.y;
    const int q0 = blockIdx.x * 128;
    const size_t bhoff = (size_t)bh * SEQ * DH;

    // stage Q tile [128][64] bf16 into smem offset 0 (SW128); 128B/thread
    {
        const uint4* src = (const uint4*)(g_qb + bhoff + (size_t)(q0 + tid) * DH);
        #pragma unroll
        for (int v = 0; v < 8; ++v)
            *(uint4*)(smem + SW128(tid * 128 + v * 16)) = src[v];
    }
    __syncthreads();

    // Q A-frags for 32 rows: qa[mi][kk][4]
    uint32_t qa[2][4][4];
    #pragma unroll
    for (int mi = 0; mi < 2; ++mi) {
        #pragma unroll
        for (int kk = 0; kk < 4; ++kk) {
            int row = warp * 32 + mi * 16 + (g & 1) * 8 + rl;
            int colb = kk * 32 + (g >> 1) * 16;
            LDSM_X4(qa[mi][kk][0], qa[mi][kk][1], qa[mi][kk][2], qa[mi][kk][3],
                    sbase + SW128(row * 128 + colb));
        }
    }

    float o[2][8][4];
    #pragma unroll
    for (int mi = 0; mi < 2; ++mi)
        #pragma unroll
        for (int j = 0; j < 8; ++j)
            #pragma unroll
            for (int i = 0; i < 4; ++i) o[mi][j][i] = 0.f;
    float l_lo[2] = {0.f, 0.f}, l_hi[2] = {0.f, 0.f};

    // cp.async: K/V tiles 128 rows x 128B; 8 K-chunks + 8 V-chunks per thread
    uint32_t soff[8];
    #pragma unroll
    for (int v = 0; v < 8; ++v)
        soff[v] = SW128(tid * 128 + v * 16);
    const char* kg = (const char*)(g_kb + bhoff) + (size_t)tid * 128;
    const char* vg = (const char*)(g_vb + bhoff) + (size_t)tid * 128;

    // prologue: tiles 0,1
    #pragma unroll
    for (int p = 0; p < 2; ++p) {
        uint32_t sb = sbase + 16384 + p * ASTG2;
        #pragma unroll
        for (int v = 0; v < 8; ++v) {
            CP16(sb + soff[v], kg + (size_t)p * 16384 + v * 16);
            CP16(sb + 16384 + soff[v], vg + (size_t)p * 16384 + v * 16);
        }
        CP_COMMIT();
    }

    for (int kt = 0; kt < NT2; ++kt) {
        if (kt == NT2 - 1) { CP_WAIT0(); } else { CP_WAIT1(); }
        __syncthreads();

        if (kt + 2 < NT2) {
            int t = kt + 2;
            uint32_t sb = sbase + 16384 + (t % 3) * ASTG2;
            #pragma unroll
            for (int v = 0; v < 8; ++v) {
                CP16(sb + soff[v], kg + (size_t)t * 16384 + v * 16);
                CP16(sb + 16384 + soff[v], vg + (size_t)t * 16384 + v * 16);
            }
            CP_COMMIT();
        }

        const uint32_t kb = sbase + 16384 + (kt % 3) * ASTG2;
        const uint32_t vb = kb + 16384;

        uint32_t aP[2][4][4];

        #pragma unroll
        for (int half = 0; half < 2; ++half) {
            const int kro = half * 64;

            // ---- S(half) = Q K^T : 16 B-LDSM -> 64 MMAs
            float c[2][8][4];
            #pragma unroll
            for (int mi = 0; mi < 2; ++mi)
                #pragma unroll
                for (int j = 0; j < 8; ++j)
                    #pragma unroll
                    for (int i = 0; i < 4; ++i) c[mi][j][i] = 0.f;

            #pragma unroll
            for (int kk = 0; kk < 4; ++kk) {
                #pragma unroll
                for (int jp = 0; jp < 4; ++jp) {
                    int row = kro + 16 * jp + (g >> 1) * 8 + rl;
                    int colb = kk * 32 + (g & 1) * 16;
                    uint32_t b0, b1, b2, b3;
                    LDSM_X4(b0, b1, b2, b3, kb + SW128(row * 128 + colb));
                    MMA_BF16(c[0][2 * jp],     qa[0][kk], b0, b1);
                    MMA_BF16(c[0][2 * jp + 1], qa[0][kk], b2, b3);
                    MMA_BF16(c[1][2 * jp],     qa[1][kk], b0, b1);
                    MMA_BF16(c[1][2 * jp + 1], qa[1][kk], b2, b3);
                }
            }

            // ---- exp + row-sum + pack
            #pragma unroll
            for (int mi = 0; mi < 2; ++mi) {
                #pragma unroll
                for (int j = 0; j < 8; ++j) {
                    float e0 = __expf(c[mi][j][0]);
                    float e1 = __expf(c[mi][j][1]);
                    float e2 = __expf(c[mi][j][2]);
                    float e3 = __expf(c[mi][j][3]);
                    l_lo[mi] += e0 + e1;
                    l_hi[mi] += e2 + e3;
                    int t = j >> 1, hi = j & 1;
                    CVT_BF2(aP[mi][t][2 * hi],     e0, e1);
                    CVT_BF2(aP[mi][t][2 * hi + 1], e2, e3);
                }
            }

            // ---- PV(half): 16 B-LDSM -> 64 MMAs
            #pragma unroll
            for (int t = 0; t < 4; ++t) {
                #pragma unroll
                for (int jj = 0; jj < 4; ++jj) {
                    int row = kro + 16 * t + (g & 1) * 8 + rl;
                    int colb = 32 * jj + (g >> 1) * 16;
                    uint32_t b0, b1, b2, b3;
                    LDSM_X4T(b0, b1, b2, b3, vb + SW128(row * 128 + colb));
                    MMA_BF16(o[0][2 * jj],     aP[0][t], b0, b1);
                    MMA_BF16(o[0][2 * jj + 1], aP[0][t], b2, b3);
                    MMA_BF16(o[1][2 * jj],     aP[1][t], b0, b1);
                    MMA_BF16(o[1][2 * jj + 1], aP[1][t], b2, b3);
                }
            }
        }
    }

    // finalize per mi: reduce l over 4 lanes, normalize, add residual
    const int bb = bh >> 4, hh = bh & 15;
    #pragma unroll
    for (int mi = 0; mi < 2; ++mi) {
        float llo = l_lo[mi], lhi = l_hi[mi];
        llo += __shfl_xor_sync(0xffffffffu, llo, 1);
        llo += __shfl_xor_sync(0xffffffffu, llo, 2);
        lhi += __shfl_xor_sync(0xffffffffu, lhi, 1);
        lhi += __shfl_xor_sync(0xffffffffu, lhi, 2);
        float inv_lo = 1.0f / llo;
        float inv_hi = 1.0f / lhi;

        int row_lo = q0 + warp * 32 + mi * 16 + gid;
        size_t base_lo = ((size_t)bb * SEQ + row_lo) * DIM + hh * DH + 2 * tid4;
        size_t base_hi = base_lo + (size_t)8 * DIM;
        #pragma unroll
        for (int j = 0; j < 8; ++j) {
            float2 xlo = *(const float2*)&x[base_lo + 8 * j];
            float2 xhi = *(const float2*)&x[base_hi + 8 * j];
            float2 rlo, rhi;
            rlo.x = o[mi][j][0] * inv_lo + xlo.x;
            rlo.y = o[mi][j][1] * inv_lo + xlo.y;
            rhi.x = o[mi][j][2] * inv_hi + xhi.x;
            rhi.y = o[mi][j][3] * inv_hi + xhi.y;
            *(float2*)&out[base_lo + 8 * j] = rlo;
            *(float2*)&out[base_hi + 8 * j] = rhi;
        }
    }
}

// ---------------------------------------------------------------------------
extern "C" void kernel_launch(void* const* d_in, const int* in_sizes, int n_in,
                              void* d_out, int out_size) {
    const float* x = (const float*)d_in[0];   // [2,2048,1024]
    const float* W = (const float*)d_in[1];   // [1024,3072]
    float* out = (float*)d_out;               // [2,2048,1024]

    cudaFuncSetAttribute(qkv_gemm, cudaFuncAttributeMaxDynamicSharedMemorySize,
                         3 * GSTG);
    cudaFuncSetAttribute(attn_mma, cudaFuncAttributeMaxDynamicSharedMemorySize,
                         16384 + 3 * ASTG2);

    cvt_kernel<<<(NX8 + NW8 + 255) / 256, 256>>>(x, W);

    dim3 gGemm(NOUT / 256, MTOT / 128);       // (12, 32)
    qkv_gemm<<<gGemm, 512, 3 * GSTG>>>(0);

    dim3 gAttn(SEQ / 128, BH);                // (16, 32)
    attn_mma<<<gAttn, 128, 16384 + 3 * ASTG2>>>(x, out);
}

// round 15
// speedup vs baseline: 1.1585x; 1.1585x over previous
#include <cuda_runtime.h>
#include <cuda_bf16.h>
#include <cstdint>
#include <math.h>

#define HEADS 16
#define DH    64
#define SEQ   2048
#define BATCH 2
#define DIM   1024
#define BH    (BATCH*HEADS)
#define NOUT  3072   // 3*HEADS*DH
#define MTOT  (BATCH*SEQ)   // 4096

// bf16 copies of the inputs (written by cvt_kernel each call)
__device__ __nv_bfloat16 g_xb[MTOT * DIM];
__device__ __nv_bfloat16 g_wb[DIM * NOUT];
// bf16 q/k/v from QKV GEMM epilogue: q pre-scaled by 0.125*log2(e); [bh][n][64].
__device__ __nv_bfloat16 g_qb[BH * SEQ * DH];
__device__ __nv_bfloat16 g_kb[BH * SEQ * DH];
__device__ __nv_bfloat16 g_vb[BH * SEQ * DH];

__device__ __forceinline__ uint32_t smem_u32(const void* p) {
    uint32_t a;
    asm("{ .reg .u64 t; cvta.to.shared.u64 t, %1; cvt.u32.u64 %0, t; }"
        : "=r"(a) : "l"(p));
    return a;
}
#define SW128(b) ((b) ^ (((b) >> 3) & 0x70))

#define LDSM_X4(r0, r1, r2, r3, a)                                         \
    asm volatile("ldmatrix.sync.aligned.m8n8.x4.shared.b16 {%0,%1,%2,%3}, [%4];" \
        : "=r"(r0), "=r"(r1), "=r"(r2), "=r"(r3) : "r"(a))
#define LDSM_X4T(r0, r1, r2, r3, a)                                        \
    asm volatile("ldmatrix.sync.aligned.m8n8.x4.trans.shared.b16 {%0,%1,%2,%3}, [%4];" \
        : "=r"(r0), "=r"(r1), "=r"(r2), "=r"(r3) : "r"(a))

#define MMA_BF16(c, a, b0, b1)                                             \
    asm volatile("mma.sync.aligned.m16n8k16.row.col.f32.bf16.bf16.f32 "    \
        "{%0,%1,%2,%3}, {%4,%5,%6,%7}, {%8,%9}, {%0,%1,%2,%3};"            \
        : "+f"((c)[0]), "+f"((c)[1]), "+f"((c)[2]), "+f"((c)[3])           \
        : "r"((a)[0]), "r"((a)[1]), "r"((a)[2]), "r"((a)[3]),              \
          "r"(b0), "r"(b1))

#define CVT_BF2(res, lo, hi) \
    asm("cvt.rn.bf16x2.f32 %0, %1, %2;" : "=r"(res) : "f"(hi), "f"(lo))

#define CP16(dst, src) \
    asm volatile("cp.async.cg.shared.global [%0], [%1], 16;" :: "r"(dst), "l"(src) : "memory")
#define CP_COMMIT() asm volatile("cp.async.commit_group;" ::: "memory")
#define CP_WAIT1()  asm volatile("cp.async.wait_group 1;" ::: "memory")
#define CP_WAIT0()  asm volatile("cp.async.wait_group 0;" ::: "memory")

// ---------------------------------------------------------------------------
// Kernel 0: fp32 -> bf16 conversion of x and W (8 elems / thread).
// ---------------------------------------------------------------------------
#define NX8 (MTOT * DIM / 8)     // 524288
#define NW8 (DIM * NOUT / 8)     // 393216
__global__ __launch_bounds__(256)
void cvt_kernel(const float* __restrict__ x, const float* __restrict__ W) {
    int i = blockIdx.x * blockDim.x + threadIdx.x;
    const float4* s4;
    uint4* d4;
    int j;
    if (i < NX8) {
        s4 = (const float4*)x; d4 = (uint4*)g_xb; j = i;
    } else if (i < NX8 + NW8) {
        s4 = (const float4*)W; d4 = (uint4*)g_wb; j = i - NX8;
    } else return;
    float4 a = s4[2 * j], b = s4[2 * j + 1];
    uint4 o;
    CVT_BF2(o.x, a.x, a.y);
    CVT_BF2(o.y, a.z, a.w);
    CVT_BF2(o.z, b.x, b.y);
    CVT_BF2(o.w, b.z, b.w);
    d4[j] = o;
}

// ---------------------------------------------------------------------------
// Kernel 1: QKV GEMM, bf16 HMMA, 3-stage cp.async pipeline (unchanged).
// CTA tile 128x256, k-step 64, 512 threads = 16 warps (4m x 4n), warp 32x64.
// ---------------------------------------------------------------------------
#define GSTG 49152
#define NKB  (DIM / 64)   // 16

__global__ __launch_bounds__(512, 1)
void qkv_gemm(int dummy) {
    extern __shared__ __align__(1024) char smem[];
    const uint32_t sbase = smem_u32(smem);

    const int tid  = threadIdx.x;
    const int lane = tid & 31;
    const int warp = tid >> 5;
    const int wm = warp >> 2;
    const int wn = warp & 3;
    const int g  = lane >> 3;
    const int rl = lane & 7;
    const int gid = lane >> 2;
    const int tid4 = lane & 3;

    const int n0 = blockIdx.x * 256;
    const int m0 = blockIdx.y * 128;

    const int arow = tid >> 2;
    const int ac2  = (tid & 3) * 2;
    const int brow = tid >> 3;
    const int bseg = tid & 7;

    const char* Ag = (const char*)(g_xb + (size_t)(m0 + arow) * DIM);
    const char* Bg = (const char*)(g_wb + (size_t)brow * NOUT + n0 + bseg * 32);

    uint32_t sa_off[2], sb_off[4];
    #pragma unroll
    for (int j = 0; j < 2; ++j)
        sa_off[j] = SW128(arow * 128 + (ac2 + j) * 16);
    #pragma unroll
    for (int j = 0; j < 4; ++j)
        sb_off[j] = 16384 + (bseg >> 1) * 8192 +
                    SW128(brow * 128 + (bseg & 1) * 64 + j * 16);

    float c[2][8][4];
    #pragma unroll
    for (int mi = 0; mi < 2; ++mi)
        #pragma unroll
        for (int nj = 0; nj < 8; ++nj)
            #pragma unroll
            for (int i = 0; i < 4; ++i) c[mi][nj][i] = 0.f;

    uint32_t a_off[2], b_off[4];
    #pragma unroll
    for (int mi = 0; mi < 2; ++mi) {
        int row = wm * 32 + mi * 16 + (g & 1) * 8 + rl;
        a_off[mi] = SW128(row * 128 + (g >> 1) * 16);
    }
    #pragma unroll
    for (int nj = 0; nj < 4; ++nj) {
        int row = (g & 1) * 8 + rl;
        b_off[nj] = 16384 + wn * 8192 + SW128(row * 128 + nj * 32 + (g >> 1) * 16);
    }

    #pragma unroll
    for (int p = 0; p < 2; ++p) {
        uint32_t sb = sbase + p * GSTG;
        const char* As = Ag + p * 128;
        const char* Bs = Bg + (size_t)p * 64 * NOUT * 2;
        #pragma unroll
        for (int j = 0; j < 2; ++j) CP16(sb + sa_off[j], As + (ac2 + j) * 16);
        #pragma unroll
        for (int j = 0; j < 4; ++j) CP16(sb + sb_off[j], Bs + j * 16);
        CP_COMMIT();
    }

    for (int kb = 0; kb < NKB; ++kb) {
        if (kb == NKB - 1) { CP_WAIT0(); } else { CP_WAIT1(); }
        __syncthreads();

        if (kb + 2 < NKB) {
            int t = kb + 2;
            uint32_t sb = sbase + (t % 3) * GSTG;
            const char* As = Ag + t * 128;
            const char* Bs = Bg + (size_t)t * 64 * NOUT * 2;
            #pragma unroll
            for (int j = 0; j < 2; ++j) CP16(sb + sa_off[j], As + (ac2 + j) * 16);
            #pragma unroll
            for (int j = 0; j < 4; ++j) CP16(sb + sb_off[j], Bs + j * 16);
            CP_COMMIT();
        }

        const uint32_t stg = sbase + (kb % 3) * GSTG;
        #pragma unroll
        for (int kk = 0; kk < 4; ++kk) {
            uint32_t a[2][4];
            uint32_t kadd = (uint32_t)((kk * 32) ^ (((kk * 32) >> 3) & 0x70));
            #pragma unroll
            for (int mi = 0; mi < 2; ++mi) {
                LDSM_X4(a[mi][0], a[mi][1], a[mi][2], a[mi][3],
                        stg + (a_off[mi] ^ kadd));
            }
            #pragma unroll
            for (int nj = 0; nj < 4; ++nj) {
                uint32_t addr = stg + b_off[nj] + kk * 16 * 128;
                uint32_t b0, b1, b2, b3;
                LDSM_X4T(b0, b1, b2, b3, addr);
                MMA_BF16(c[0][2 * nj],     a[0], b0, b1);
                MMA_BF16(c[0][2 * nj + 1], a[0], b2, b3);
                MMA_BF16(c[1][2 * nj],     a[1], b0, b1);
                MMA_BF16(c[1][2 * nj + 1], a[1], b2, b3);
            }
        }
    }

    // q gets 0.125 * log2(e) so the softmax can use exp2 (MUFU.EX2 directly)
    const int sec = n0 >> 10;
    const float s = (sec == 0) ? 0.125f * 1.4426950408889634f : 1.0f;
    __nv_bfloat16* gout = (sec == 0) ? g_qb : (sec == 1) ? g_kb : g_vb;
    const int hh = ((n0 & 1023) >> 6) + wn;

    #pragma unroll
    for (int mi = 0; mi < 2; ++mi) {
        #pragma unroll
        for (int r8 = 0; r8 < 2; ++r8) {
            int m = m0 + wm * 32 + mi * 16 + r8 * 8 + gid;
            int bb = m >> 11;
            int n  = m & (SEQ - 1);
            __nv_bfloat16* dst =
                gout + ((size_t)(bb * HEADS + hh) * SEQ + n) * DH + tid4 * 2;
            #pragma unroll
            for (int nj = 0; nj < 8; ++nj) {
                uint32_t p;
                CVT_BF2(p, c[mi][nj][r8 * 2] * s, c[mi][nj][r8 * 2 + 1] * s);
                *(uint32_t*)(dst + nj * 8) = p;
            }
        }
    }
}

// ---------------------------------------------------------------------------
// Kernel 2: HMMA flash attention (R12 shape: 8 warps x 16 q-rows), 128-key
// tiles as two 64-key halves, WARP-PARITY STAGGERED: even warps do halves
// (0,1), odd warps (1,0), so exp phases of different warps overlap with
// MMA phases. exp2f (q pre-scaled by log2e). 3-stage cp.async, 112KB smem.
// ---------------------------------------------------------------------------
#define ASTG2 32768
#define NT2   (SEQ / 128)   // 16

__global__ __launch_bounds__(256, 2)
void attn_mma(const float* __restrict__ x, float* __restrict__ out) {
    extern __shared__ __align__(1024) char smem[];
    const uint32_t sbase = smem_u32(smem);

    const int tid  = threadIdx.x;
    const int lane = tid & 31;
    const int warp = tid >> 5;
    const int g    = lane >> 3;
    const int rl   = lane & 7;
    const int gid  = lane >> 2;
    const int tid4 = lane & 3;
    const int wpar = warp & 1;        // half-order stagger parity

    const int bh = blockIdx.y;
    const int q0 = blockIdx.x * 128;
    const size_t bhoff = (size_t)bh * SEQ * DH;

    // stage Q tile [128][64] bf16 into smem offset 0 (SW128)
    {
        const uint4* src = (const uint4*)(g_qb + bhoff + (size_t)q0 * DH);
        int row = tid >> 1;
        int c16 = (tid & 1) * 4;
        #pragma unroll
        for (int v = 0; v < 4; ++v) {
            *(uint4*)(smem + SW128(row * 128 + (c16 + v) * 16)) =
                src[row * 8 + c16 + v];
        }
    }
    __syncthreads();

    uint32_t qa[4][4];
    #pragma unroll
    for (int kk = 0; kk < 4; ++kk) {
        int row = warp * 16 + (g & 1) * 8 + rl;
        int colb = kk * 32 + (g >> 1) * 16;
        uint32_t a = sbase + SW128(row * 128 + colb);
        LDSM_X4(qa[kk][0], qa[kk][1], qa[kk][2], qa[kk][3], a);
    }

    float o[8][4];
    #pragma unroll
    for (int j = 0; j < 8; ++j)
        #pragma unroll
        for (int i = 0; i < 4; ++i) o[j][i] = 0.f;
    float l_lo = 0.f, l_hi = 0.f;

    // cp.async mapping: 128 rows x 128B per K (and V); 4 chunks per thread each
    const int krow = tid >> 1;              // 0..127
    const int kc4  = (tid & 1) * 4;         // chunk 0 or 4
    uint32_t soff[4];
    #pragma unroll
    for (int v = 0; v < 4; ++v)
        soff[v] = SW128(krow * 128 + (kc4 + v) * 16);
    const char* kg = (const char*)(g_kb + bhoff) + (size_t)krow * 128 + kc4 * 16;
    const char* vg = (const char*)(g_vb + bhoff) + (size_t)krow * 128 + kc4 * 16;

    // prologue: issue tiles 0,1
    #pragma unroll
    for (int p = 0; p < 2; ++p) {
        uint32_t sb = sbase + 16384 + p * ASTG2;
        #pragma unroll
        for (int v = 0; v < 4; ++v) {
            CP16(sb + soff[v], kg + (size_t)p * 16384 + v * 16);
            CP16(sb + 16384 + soff[v], vg + (size_t)p * 16384 + v * 16);
        }
        CP_COMMIT();
    }

    for (int kt = 0; kt < NT2; ++kt) {
        if (kt == NT2 - 1) { CP_WAIT0(); } else { CP_WAIT1(); }
        __syncthreads();

        if (kt + 2 < NT2) {
            int t = kt + 2;
            uint32_t sb = sbase + 16384 + (t % 3) * ASTG2;
            #pragma unroll
            for (int v = 0; v < 4; ++v) {
                CP16(sb + soff[v], kg + (size_t)t * 16384 + v * 16);
                CP16(sb + 16384 + soff[v], vg + (size_t)t * 16384 + v * 16);
            }
            CP_COMMIT();
        }

        const uint32_t kb = sbase + 16384 + (kt % 3) * ASTG2;
        const uint32_t vb = kb + 16384;

        #pragma unroll
        for (int h2 = 0; h2 < 2; ++h2) {
            const int kro = (h2 ^ wpar) * 64;   // staggered half order

            // ---- S(half) = Q K^T
            float c[8][4];
            #pragma unroll
            for (int j = 0; j < 8; ++j)
                #pragma unroll
                for (int i = 0; i < 4; ++i) c[j][i] = 0.f;

            #pragma unroll
            for (int kk = 0; kk < 4; ++kk) {
                #pragma unroll
                for (int jp = 0; jp < 4; ++jp) {
                    int row = kro + 16 * jp + (g >> 1) * 8 + rl;
                    int colb = kk * 32 + (g & 1) * 16;
                    uint32_t b0, b1, b2, b3;
                    LDSM_X4(b0, b1, b2, b3, kb + SW128(row * 128 + colb));
                    MMA_BF16(c[2 * jp],     qa[kk], b0, b1);
                    MMA_BF16(c[2 * jp + 1], qa[kk], b2, b3);
                }
            }

            // ---- exp2 + row-sum + pack (q carries log2e)
            uint32_t aP[4][4];
            #pragma unroll
            for (int j = 0; j < 8; ++j) {
                float e0 = exp2f(c[j][0]);
                float e1 = exp2f(c[j][1]);
                float e2 = exp2f(c[j][2]);
                float e3 = exp2f(c[j][3]);
                l_lo += e0 + e1;
                l_hi += e2 + e3;
                int t = j >> 1, hi = j & 1;
                CVT_BF2(aP[t][2 * hi],     e0, e1);
                CVT_BF2(aP[t][2 * hi + 1], e2, e3);
            }

            // ---- PV(half)
            #pragma unroll
            for (int t = 0; t < 4; ++t) {
                #pragma unroll
                for (int jj = 0; jj < 4; ++jj) {
                    int row = kro + 16 * t + (g & 1) * 8 + rl;
                    int colb = 32 * jj + (g >> 1) * 16;
                    uint32_t b0, b1, b2, b3;
                    LDSM_X4T(b0, b1, b2, b3, vb + SW128(row * 128 + colb));
                    MMA_BF16(o[2 * jj],     aP[t], b0, b1);
                    MMA_BF16(o[2 * jj + 1], aP[t], b2, b3);
                }
            }
        }
    }

    l_lo += __shfl_xor_sync(0xffffffffu, l_lo, 1);
    l_lo += __shfl_xor_sync(0xffffffffu, l_lo, 2);
    l_hi += __shfl_xor_sync(0xffffffffu, l_hi, 1);
    l_hi += __shfl_xor_sync(0xffffffffu, l_hi, 2);
    float inv_lo = 1.0f / l_lo;
    float inv_hi = 1.0f / l_hi;

    const int bb = bh >> 4, hh = bh & 15;
    int row_lo = q0 + warp * 16 + gid;
    size_t base_lo = ((size_t)bb * SEQ + row_lo) * DIM + hh * DH + 2 * tid4;
    size_t base_hi = base_lo + (size_t)8 * DIM;
    #pragma unroll
    for (int j = 0; j < 8; ++j) {
        float2 xlo = *(const float2*)&x[base_lo + 8 * j];
        float2 xhi = *(const float2*)&x[base_hi + 8 * j];
        float2 rlo, rhi;
        rlo.x = o[j][0] * inv_lo + xlo.x;
        rlo.y = o[j][1] * inv_lo + xlo.y;
        rhi.x = o[j][2] * inv_hi + xhi.x;
        rhi.y = o[j][3] * inv_hi + xhi.y;
        *(float2*)&out[base_lo + 8 * j] = rlo;
        *(float2*)&out[base_hi + 8 * j] = rhi;
    }
}

// ---------------------------------------------------------------------------
extern "C" void kernel_launch(void* const* d_in, const int* in_sizes, int n_in,
                              void* d_out, int out_size) {
    const float* x = (const float*)d_in[0];   // [2,2048,1024]
    const float* W = (const float*)d_in[1];   // [1024,3072]
    float* out = (float*)d_out;               // [2,2048,1024]

    cudaFuncSetAttribute(qkv_gemm, cudaFuncAttributeMaxDynamicSharedMemorySize,
                         3 * GSTG);
    cudaFuncSetAttribute(attn_mma, cudaFuncAttributeMaxDynamicSharedMemorySize,
                         16384 + 3 * ASTG2);

    cvt_kernel<<<(NX8 + NW8 + 255) / 256, 256>>>(x, W);

    dim3 gGemm(NOUT / 256, MTOT / 128);       // (12, 32)
    qkv_gemm<<<gGemm, 512, 3 * GSTG>>>(0);

    dim3 gAttn(SEQ / 128, BH);                // (16, 32)
    attn_mma<<<gAttn, 256, 16384 + 3 * ASTG2>>>(x, out);
}

// round 17
// speedup vs baseline: 1.1786x; 1.0174x over previous
#include <cuda_runtime.h>
#include <cuda_bf16.h>
#include <cstdint>
#include <math.h>

#define HEADS 16
#define DH    64
#define SEQ   2048
#define BATCH 2
#define DIM   1024
#define BH    (BATCH*HEADS)
#define NOUT  3072   // 3*HEADS*DH
#define MTOT  (BATCH*SEQ)   // 4096

// bf16 copies of the inputs (written by cvt_kernel each call)
__device__ __nv_bfloat16 g_xb[MTOT * DIM];
__device__ __nv_bfloat16 g_wb[DIM * NOUT];
// bf16 q/k/v from QKV GEMM epilogue: q pre-scaled by 0.125*log2(e); [bh][n][64].
__device__ __nv_bfloat16 g_qb[BH * SEQ * DH];
__device__ __nv_bfloat16 g_kb[BH * SEQ * DH];
__device__ __nv_bfloat16 g_vb[BH * SEQ * DH];

__device__ __forceinline__ uint32_t smem_u32(const void* p) {
    uint32_t a;
    asm("{ .reg .u64 t; cvta.to.shared.u64 t, %1; cvt.u32.u64 %0, t; }"
        : "=r"(a) : "l"(p));
    return a;
}
#define SW128(b) ((b) ^ (((b) >> 3) & 0x70))

#define LDSM_X4(r0, r1, r2, r3, a)                                         \
    asm volatile("ldmatrix.sync.aligned.m8n8.x4.shared.b16 {%0,%1,%2,%3}, [%4];" \
        : "=r"(r0), "=r"(r1), "=r"(r2), "=r"(r3) : "r"(a))
#define LDSM_X4T(r0, r1, r2, r3, a)                                        \
    asm volatile("ldmatrix.sync.aligned.m8n8.x4.trans.shared.b16 {%0,%1,%2,%3}, [%4];" \
        : "=r"(r0), "=r"(r1), "=r"(r2), "=r"(r3) : "r"(a))

#define MMA_BF16(c, a, b0, b1)                                             \
    asm volatile("mma.sync.aligned.m16n8k16.row.col.f32.bf16.bf16.f32 "    \
        "{%0,%1,%2,%3}, {%4,%5,%6,%7}, {%8,%9}, {%0,%1,%2,%3};"            \
        : "+f"((c)[0]), "+f"((c)[1]), "+f"((c)[2]), "+f"((c)[3])           \
        : "r"((a)[0]), "r"((a)[1]), "r"((a)[2]), "r"((a)[3]),              \
          "r"(b0), "r"(b1))

#define CVT_BF2(res, lo, hi) \
    asm("cvt.rn.bf16x2.f32 %0, %1, %2;" : "=r"(res) : "f"(hi), "f"(lo))

#define CP16(dst, src) \
    asm volatile("cp.async.cg.shared.global [%0], [%1], 16;" :: "r"(dst), "l"(src) : "memory")
#define CP_COMMIT() asm volatile("cp.async.commit_group;" ::: "memory")
#define CP_WAIT1()  asm volatile("cp.async.wait_group 1;" ::: "memory")
#define CP_WAIT0()  asm volatile("cp.async.wait_group 0;" ::: "memory")

// ---------------------------------------------------------------------------
// Kernel 0: fp32 -> bf16 conversion of x and W (8 elems / thread).
// ---------------------------------------------------------------------------
#define NX8 (MTOT * DIM / 8)     // 524288
#define NW8 (DIM * NOUT / 8)     // 393216
__global__ __launch_bounds__(256)
void cvt_kernel(const float* __restrict__ x, const float* __restrict__ W) {
    int i = blockIdx.x * blockDim.x + threadIdx.x;
    const float4* s4;
    uint4* d4;
    int j;
    if (i < NX8) {
        s4 = (const float4*)x; d4 = (uint4*)g_xb; j = i;
    } else if (i < NX8 + NW8) {
        s4 = (const float4*)W; d4 = (uint4*)g_wb; j = i - NX8;
    } else return;
    float4 a = s4[2 * j], b = s4[2 * j + 1];
    uint4 o;
    CVT_BF2(o.x, a.x, a.y);
    CVT_BF2(o.y, a.z, a.w);
    CVT_BF2(o.z, b.x, b.y);
    CVT_BF2(o.w, b.z, b.w);
    d4[j] = o;
}

// ---------------------------------------------------------------------------
// Kernel 1: QKV GEMM, bf16 HMMA, 3-stage cp.async pipeline (R10/R12 verified).
// CTA tile 128x256, k-step 64, 512 threads = 16 warps (4m x 4n), warp 32x64.
// ---------------------------------------------------------------------------
#define GSTG 49152
#define NKB  (DIM / 64)   // 16

__global__ __launch_bounds__(512, 1)
void qkv_gemm(int dummy) {
    extern __shared__ __align__(1024) char smem[];
    const uint32_t sbase = smem_u32(smem);
    const uint32_t bbase = sbase + 16384;

    const int tid  = threadIdx.x;
    const int lane = tid & 31;
    const int warp = tid >> 5;
    const int wm = warp >> 2;
    const int wn = warp & 3;
    const int g  = lane >> 3;
    const int rl = lane & 7;
    const int gid = lane >> 2;
    const int tid4 = lane & 3;

    const int n0 = blockIdx.x * 256;
    const int m0 = blockIdx.y * 128;

    const int arow = tid >> 2;
    const int ac2  = (tid & 3) * 2;
    const int brow = tid >> 3;
    const int bseg = tid & 7;

    const char* Ag = (const char*)(g_xb + (size_t)(m0 + arow) * DIM);
    const char* Bg = (const char*)(g_wb + (size_t)brow * NOUT + n0 + bseg * 32);

    uint32_t sa_off[2], sb_off[4];
    #pragma unroll
    for (int j = 0; j < 2; ++j)
        sa_off[j] = SW128(arow * 128 + (ac2 + j) * 16);
    #pragma unroll
    for (int j = 0; j < 4; ++j)
        sb_off[j] = 16384 + (bseg >> 1) * 8192 +
                    SW128(brow * 128 + (bseg & 1) * 64 + j * 16);

    float c[2][8][4];
    #pragma unroll
    for (int mi = 0; mi < 2; ++mi)
        #pragma unroll
        for (int nj = 0; nj < 8; ++nj)
            #pragma unroll
            for (int i = 0; i < 4; ++i) c[mi][nj][i] = 0.f;

    uint32_t a_off[2], b_off[4];
    #pragma unroll
    for (int mi = 0; mi < 2; ++mi) {
        int row = wm * 32 + mi * 16 + (g & 1) * 8 + rl;
        a_off[mi] = SW128(row * 128 + (g >> 1) * 16);
    }
    #pragma unroll
    for (int nj = 0; nj < 4; ++nj) {
        int row = (g & 1) * 8 + rl;
        b_off[nj] = 16384 + wn * 8192 + SW128(row * 128 + nj * 32 + (g >> 1) * 16);
    }

    #pragma unroll
    for (int p = 0; p < 2; ++p) {
        uint32_t sb = sbase + p * GSTG;
        const char* As = Ag + p * 128;
        const char* Bs = Bg + (size_t)p * 64 * NOUT * 2;
        #pragma unroll
        for (int j = 0; j < 2; ++j) CP16(sb + sa_off[j], As + (ac2 + j) * 16);
        #pragma unroll
        for (int j = 0; j < 4; ++j) CP16(sb + sb_off[j], Bs + j * 16);
        CP_COMMIT();
    }

    for (int kb = 0; kb < NKB; ++kb) {
        if (kb == NKB - 1) { CP_WAIT0(); } else { CP_WAIT1(); }
        __syncthreads();

        if (kb + 2 < NKB) {
            int t = kb + 2;
            uint32_t sb = sbase + (t % 3) * GSTG;
            const char* As = Ag + t * 128;
            const char* Bs = Bg + (size_t)t * 64 * NOUT * 2;
            #pragma unroll
            for (int j = 0; j < 2; ++j) CP16(sb + sa_off[j], As + (ac2 + j) * 16);
            #pragma unroll
            for (int j = 0; j < 4; ++j) CP16(sb + sb_off[j], Bs + j * 16);
            CP_COMMIT();
        }

        const uint32_t stg = sbase + (kb % 3) * GSTG;
        #pragma unroll
        for (int kk = 0; kk < 4; ++kk) {
            uint32_t a[2][4];
            uint32_t kadd = (uint32_t)((kk * 32) ^ (((kk * 32) >> 3) & 0x70));
            #pragma unroll
            for (int mi = 0; mi < 2; ++mi) {
                LDSM_X4(a[mi][0], a[mi][1], a[mi][2], a[mi][3],
                        stg + (a_off[mi] ^ kadd));
            }
            #pragma unroll
            for (int nj = 0; nj < 4; ++nj) {
                uint32_t addr = stg + b_off[nj] + kk * 16 * 128;
                uint32_t b0, b1, b2, b3;
                LDSM_X4T(b0, b1, b2, b3, addr);
                MMA_BF16(c[0][2 * nj],     a[0], b0, b1);
                MMA_BF16(c[0][2 * nj + 1], a[0], b2, b3);
                MMA_BF16(c[1][2 * nj],     a[1], b0, b1);
                MMA_BF16(c[1][2 * nj + 1], a[1], b2, b3);
            }
        }
    }

    // epilogue: scatter bf16 into q/k/v. q carries 0.125*log2(e) for exp2.
    const int sec = n0 >> 10;
    const float s = (sec == 0) ? 0.125f * 1.4426950408889634f : 1.0f;
    __nv_bfloat16* gout = (sec == 0) ? g_qb : (sec == 1) ? g_kb : g_vb;
    const int hh = ((n0 & 1023) >> 6) + wn;

    #pragma unroll
    for (int mi = 0; mi < 2; ++mi) {
        #pragma unroll
        for (int r8 = 0; r8 < 2; ++r8) {
            int m = m0 + wm * 32 + mi * 16 + r8 * 8 + gid;
            int bb = m >> 11;
            int n  = m & (SEQ - 1);
            __nv_bfloat16* dst =
                gout + ((size_t)(bb * HEADS + hh) * SEQ + n) * DH + tid4 * 2;
            #pragma unroll
            for (int nj = 0; nj < 8; ++nj) {
                uint32_t p;
                CVT_BF2(p, c[mi][nj][r8 * 2] * s, c[mi][nj][r8 * 2 + 1] * s);
                *(uint32_t*)(dst + nj * 8) = p;
            }
        }
    }
}

// ---------------------------------------------------------------------------
// Kernel 2: HMMA flash attention (R12 winner, exp2 softmax). 8 warps x 16
// q-rows, 128-key tiles as two sequential halves with PV0||S1 interleave,
// 3-stage cp.async; smem = Q 16KB + 3 x 32KB = 112KB; 2 CTAs/SM.
// ---------------------------------------------------------------------------
#define ASTG2 32768
#define NT2   (SEQ / 128)   // 16

__global__ __launch_bounds__(256, 2)
void attn_mma(const float* __restrict__ x, float* __restrict__ out) {
    extern __shared__ __align__(1024) char smem[];
    const uint32_t sbase = smem_u32(smem);

    const int tid  = threadIdx.x;
    const int lane = tid & 31;
    const int warp = tid >> 5;
    const int g    = lane >> 3;
    const int rl   = lane & 7;
    const int gid  = lane >> 2;
    const int tid4 = lane & 3;

    const int bh = blockIdx.y;
    const int q0 = blockIdx.x * 128;
    const size_t bhoff = (size_t)bh * SEQ * DH;

    // stage Q tile [128][64] bf16 into smem offset 0 (SW128)
    {
        const uint4* src = (const uint4*)(g_qb + bhoff + (size_t)q0 * DH);
        int row = tid >> 1;
        int c16 = (tid & 1) * 4;
        #pragma unroll
        for (int v = 0; v < 4; ++v) {
            *(uint4*)(smem + SW128(row * 128 + (c16 + v) * 16)) =
                src[row * 8 + c16 + v];
        }
    }
    __syncthreads();

    uint32_t qa[4][4];
    #pragma unroll
    for (int kk = 0; kk < 4; ++kk) {
        int row = warp * 16 + (g & 1) * 8 + rl;
        int colb = kk * 32 + (g >> 1) * 16;
        uint32_t a = sbase + SW128(row * 128 + colb);
        LDSM_X4(qa[kk][0], qa[kk][1], qa[kk][2], qa[kk][3], a);
    }

    float o[8][4];
    #pragma unroll
    for (int j = 0; j < 8; ++j)
        #pragma unroll
        for (int i = 0; i < 4; ++i) o[j][i] = 0.f;
    float l_lo = 0.f, l_hi = 0.f;

    const int krow = tid >> 1;              // 0..127
    const int kc4  = (tid & 1) * 4;         // chunk 0 or 4
    uint32_t soff[4];
    #pragma unroll
    for (int v = 0; v < 4; ++v)
        soff[v] = SW128(krow * 128 + (kc4 + v) * 16);
    const char* kg = (const char*)(g_kb + bhoff) + (size_t)krow * 128 + kc4 * 16;
    const char* vg = (const char*)(g_vb + bhoff) + (size_t)krow * 128 + kc4 * 16;

    // prologue: issue tiles 0,1
    #pragma unroll
    for (int p = 0; p < 2; ++p) {
        uint32_t sb = sbase + 16384 + p * ASTG2;
        #pragma unroll
        for (int v = 0; v < 4; ++v) {
            CP16(sb + soff[v], kg + (size_t)p * 16384 + v * 16);
            CP16(sb + 16384 + soff[v], vg + (size_t)p * 16384 + v * 16);
        }
        CP_COMMIT();
    }

    for (int kt = 0; kt < NT2; ++kt) {
        if (kt == NT2 - 1) { CP_WAIT0(); } else { CP_WAIT1(); }
        __syncthreads();

        if (kt + 2 < NT2) {
            int t = kt + 2;
            uint32_t sb = sbase + 16384 + (t % 3) * ASTG2;
            #pragma unroll
            for (int v = 0; v < 4; ++v) {
                CP16(sb + soff[v], kg + (size_t)t * 16384 + v * 16);
                CP16(sb + 16384 + soff[v], vg + (size_t)t * 16384 + v * 16);
            }
            CP_COMMIT();
        }

        const uint32_t kb = sbase + 16384 + (kt % 3) * ASTG2;
        const uint32_t vb = kb + 16384;

        // ================= half 0: S =================
        float c[8][4];
        #pragma unroll
        for (int j = 0; j < 8; ++j)
            #pragma unroll
            for (int i = 0; i < 4; ++i) c[j][i] = 0.f;

        #pragma unroll
        for (int kk = 0; kk < 4; ++kk) {
            #pragma unroll
            for (int jp = 0; jp < 4; ++jp) {
                int row = 16 * jp + (g >> 1) * 8 + rl;       // keys 0..63
                int colb = kk * 32 + (g & 1) * 16;
                uint32_t b0, b1, b2, b3;
                LDSM_X4(b0, b1, b2, b3, kb + SW128(row * 128 + colb));
                MMA_BF16(c[2 * jp],     qa[kk], b0, b1);
                MMA_BF16(c[2 * jp + 1], qa[kk], b2, b3);
            }
        }

        // exp0 (exp2: q carries log2e) + pack
        uint32_t aP[4][4];
        #pragma unroll
        for (int j = 0; j < 8; ++j) {
            float e0 = exp2f(c[j][0]);
            float e1 = exp2f(c[j][1]);
            float e2 = exp2f(c[j][2]);
            float e3 = exp2f(c[j][3]);
            l_lo += e0 + e1;
            l_hi += e2 + e3;
            int t = j >> 1, hi = j & 1;
            CVT_BF2(aP[t][2 * hi],     e0, e1);
            CVT_BF2(aP[t][2 * hi + 1], e2, e3);
        }

        // ====== PV(half0) then S(half1): independent, continuous stream ======
        #pragma unroll
        for (int t = 0; t < 4; ++t) {
            #pragma unroll
            for (int jjp = 0; jjp < 4; ++jjp) {
                int row = 16 * t + (g & 1) * 8 + rl;          // keys 0..63
                int colb = 32 * jjp + (g >> 1) * 16;
                uint32_t b0, b1, b2, b3;
                LDSM_X4T(b0, b1, b2, b3, vb + SW128(row * 128 + colb));
                MMA_BF16(o[2 * jjp],     aP[t], b0, b1);
                MMA_BF16(o[2 * jjp + 1], aP[t], b2, b3);
            }
        }

        #pragma unroll
        for (int j = 0; j < 8; ++j)
            #pragma unroll
            for (int i = 0; i < 4; ++i) c[j][i] = 0.f;

        #pragma unroll
        for (int kk = 0; kk < 4; ++kk) {
            #pragma unroll
            for (int jp = 0; jp < 4; ++jp) {
                int row = 64 + 16 * jp + (g >> 1) * 8 + rl;   // keys 64..127
                int colb = kk * 32 + (g & 1) * 16;
                uint32_t b0, b1, b2, b3;
                LDSM_X4(b0, b1, b2, b3, kb + SW128(row * 128 + colb));
                MMA_BF16(c[2 * jp],     qa[kk], b0, b1);
                MMA_BF16(c[2 * jp + 1], qa[kk], b2, b3);
            }
        }

        // exp1 + pack
        #pragma unroll
        for (int j = 0; j < 8; ++j) {
            float e0 = exp2f(c[j][0]);
            float e1 = exp2f(c[j][1]);
            float e2 = exp2f(c[j][2]);
            float e3 = exp2f(c[j][3]);
            l_lo += e0 + e1;
            l_hi += e2 + e3;
            int t = j >> 1, hi = j & 1;
            CVT_BF2(aP[t][2 * hi],     e0, e1);
            CVT_BF2(aP[t][2 * hi + 1], e2, e3);
        }

        // PV(half1)
        #pragma unroll
        for (int t = 0; t < 4; ++t) {
            #pragma unroll
            for (int jjp = 0; jjp < 4; ++jjp) {
                int row = 64 + 16 * t + (g & 1) * 8 + rl;     // keys 64..127
                int colb = 32 * jjp + (g >> 1) * 16;
                uint32_t b0, b1, b2, b3;
                LDSM_X4T(b0, b1, b2, b3, vb + SW128(row * 128 + colb));
                MMA_BF16(o[2 * jjp],     aP[t], b0, b1);
                MMA_BF16(o[2 * jjp + 1], aP[t], b2, b3);
            }
        }
    }

    l_lo += __shfl_xor_sync(0xffffffffu, l_lo, 1);
    l_lo += __shfl_xor_sync(0xffffffffu, l_lo, 2);
    l_hi += __shfl_xor_sync(0xffffffffu, l_hi, 1);
    l_hi += __shfl_xor_sync(0xffffffffu, l_hi, 2);
    float inv_lo = 1.0f / l_lo;
    float inv_hi = 1.0f / l_hi;

    const int bb = bh >> 4, hh = bh & 15;
    int row_lo = q0 + warp * 16 + gid;
    size_t base_lo = ((size_t)bb * SEQ + row_lo) * DIM + hh * DH + 2 * tid4;
    size_t base_hi = base_lo + (size_t)8 * DIM;
    #pragma unroll
    for (int j = 0; j < 8; ++j) {
        float2 xlo = *(const float2*)&x[base_lo + 8 * j];
        float2 xhi = *(const float2*)&x[base_hi + 8 * j];
        float2 rlo, rhi;
        rlo.x = o[j][0] * inv_lo + xlo.x;
        rlo.y = o[j][1] * inv_lo + xlo.y;
        rhi.x = o[j][2] * inv_hi + xhi.x;
        rhi.y = o[j][3] * inv_hi + xhi.y;
        *(float2*)&out[base_lo + 8 * j] = rlo;
        *(float2*)&out[base_hi + 8 * j] = rhi;
    }
}

// ---------------------------------------------------------------------------
extern "C" void kernel_launch(void* const* d_in, const int* in_sizes, int n_in,
                              void* d_out, int out_size) {
    const float* x = (const float*)d_in[0];   // [2,2048,1024]
    const float* W = (const float*)d_in[1];   // [1024,3072]
    float* out = (float*)d_out;               // [2,2048,1024]

    cudaFuncSetAttribute(qkv_gemm, cudaFuncAttributeMaxDynamicSharedMemorySize,
                         3 * GSTG);
    cudaFuncSetAttribute(attn_mma, cudaFuncAttributeMaxDynamicSharedMemorySize,
                         16384 + 3 * ASTG2);

    cvt_kernel<<<(NX8 + NW8 + 255) / 256, 256>>>(x, W);

    dim3 gGemm(NOUT / 256, MTOT / 128);       // (12, 32)
    qkv_gemm<<<gGemm, 512, 3 * GSTG>>>(0);

    dim3 gAttn(SEQ / 128, BH);                // (16, 32)
    attn_mma<<<gAttn, 256, 16384 + 3 * ASTG2>>>(x, out);
}